// round 14
// baseline (speedup 1.0000x reference)
#include <cuda_runtime.h>
#include <cuda_fp16.h>
#include <cstdint>

// Problem constants
#define B_   8
#define C_   128
#define H_   64
#define W_   64
#define COUT 128
#define KO   18
#define CK   1152          // C_*9, K reordered as k9*128 + c
#define KC   64            // K per chunk
#define NCHUNK (CK / KC)   // 18
#define MOFF 32            // KO padded to 32 for MMA

__device__ __forceinline__ uint32_t smem_to_u32(const void* p) {
    uint32_t a;
    asm("{ .reg .u64 t; cvta.to.shared.u64 t, %1; cvt.u32.u64 %0, t; }" : "=r"(a) : "l"(p));
    return a;
}

// ldmatrix x4 (non-transposed)
#define LDSM4(r0, r1, r2, r3, addr) \
    asm volatile("ldmatrix.sync.aligned.m8n8.x4.shared.b16 {%0,%1,%2,%3}, [%4];" \
                 : "=r"(r0), "=r"(r1), "=r"(r2), "=r"(r3) : "r"(addr))

// fp16 mma with fp32 accumulate
#define MMA16816(c, a0, a1, a2, a3, b0, b1) \
    asm volatile("mma.sync.aligned.m16n8k16.row.col.f32.f16.f16.f32 " \
                 "{%0,%1,%2,%3},{%4,%5,%6,%7},{%8,%9},{%0,%1,%2,%3};" \
                 : "+f"((c)[0]), "+f"((c)[1]), "+f"((c)[2]), "+f"((c)[3]) \
                 : "r"(a0), "r"(a1), "r"(a2), "r"(a3), "r"(b0), "r"(b1))

// swizzled tile offset for k_offmma (128B rows, XOR on 16B granule)
__device__ __forceinline__ uint32_t sw_off(int row, int g16) {
    return (uint32_t)(row * 128 + ((g16 ^ (row & 7)) << 4));
}

// ---------------- device scratch ----------------
__device__ float g_off[B_ * KO * H_ * W_];
__device__ __align__(16) __half g_wh[COUT * CK];            // deform weights fp16, K = k9*128 + c
__device__ __align__(16) __half g_woh[MOFF * CK];           // offset-conv weights fp16, M padded
__device__ __align__(16) __half g_xh[B_ * H_ * W_ * C_];    // NHWC fp16 x (channel-last)

// ---------------- kernel 0a: fp16 deform weights, k9-major reorder ----------------
__global__ void k_prep_w(const float* __restrict__ w_def) {
    int i = blockIdx.x * blockDim.x + threadIdx.x;
    if (i < COUT * CK) {
        int cout = i / CK;
        int rem  = i - cout * CK;
        int k9   = rem >> 7;
        int c    = rem & 127;
        g_wh[i] = __float2half(w_def[(cout * C_ + c) * 9 + k9]);
    }
}

// ---------------- kernel 0b: fp16 offset weights, k9-major, M padded to 32 ----------------
__global__ void k_prep_woff(const float* __restrict__ w_off) {
    int i = blockIdx.x * blockDim.x + threadIdx.x;
    if (i < MOFF * CK) {
        int m   = i / CK;
        int rem = i - m * CK;
        int k9  = rem >> 7;
        int c   = rem & 127;
        float v = (m < KO) ? w_off[(m * C_ + c) * 9 + k9] : 0.f;
        g_woh[i] = __float2half(v);
    }
}

// ---------------- kernel 0c: NCHW fp32 -> NHWC fp16 transpose ----------------
// grid = B_*H_ (one (b,h) slab: 128c x 64w), blockDim = 256
__global__ void k_prep_xh(const float* __restrict__ x) {
    __shared__ __half sm[128][66];   // [c][w], pad 2 (33-word row stride, odd)
    int b  = blockIdx.x >> 6;
    int h  = blockIdx.x & 63;
    int tid = threadIdx.x;
    int c4 = tid >> 6;               // 0..3
    int w  = tid & 63;

    #pragma unroll
    for (int cb = 0; cb < 128; cb += 4) {
        int c = cb + c4;
        sm[c][w] = __float2half(x[((size_t)(b * C_ + c) * H_ + h) * W_ + w]);
    }
    __syncthreads();

    // write NHWC: dst[((b*H+h)*W + w)*128 + c], 16B chunks
    __half* dst = g_xh + ((size_t)(b * H_ + h) * W_) * C_;
    #pragma unroll
    for (int j = tid; j < 1024; j += 256) {    // 64 w x 16 granules
        int w2 = j >> 4;
        int g  = j & 15;
        __half tmp[8];
        #pragma unroll
        for (int e = 0; e < 8; e++) tmp[e] = sm[g * 8 + e][w2];
        *(uint4*)(dst + (size_t)w2 * C_ + g * 8) = *(uint4*)tmp;
    }
}

// ---------------- kernel 1: offsets conv via fp16 mma.sync (R13 version, kept) ----------------
__global__ void __launch_bounds__(256)
k_offmma(const float* __restrict__ x, const float* __restrict__ b_off) {
    __shared__ __align__(16) char smA[MOFF * 128];   // 4096
    __shared__ __align__(16) char smB[64 * 128];     // 8192
    uint32_t sbA = smem_to_u32(smA);
    uint32_t sbB = smem_to_u32(smB);

    int b   = blockIdx.x >> 6;
    int ho  = blockIdx.x & 63;
    int tid = threadIdx.x;
    int wid = tid >> 5;
    int lane = tid & 31;

    const int wm = wid & 1;
    const int wn = wid >> 1;

    float c[2][4];
    #pragma unroll
    for (int i = 0; i < 2; i++)
        #pragma unroll
        for (int j = 0; j < 4; j++) c[i][j] = 0.f;

    const int n  = tid & 63;
    const int t4 = tid >> 6;

    const int g8 = lane >> 3;
    const int lr = lane & 7;
    const int a_row = wm * 16 + lr + (g8 & 1) * 8;
    const int b_row = wn * 16 + lr + (g8 >> 1) * 8;
    const int ar7 = a_row & 7;
    const int br7 = b_row & 7;
    const int agl = g8 >> 1;
    const int bgl = g8 & 1;

    const int a_m  = tid >> 3;
    const int a_g  = tid & 7;

    for (int chunk = 0; chunk < NCHUNK; chunk++) {
        const int k9 = chunk >> 1;
        const int c0 = (chunk & 1) * 64;
        const int ky = k9 / 3;
        const int kx = k9 - ky * 3;

        __syncthreads();

        {
            const char* src = (const char*)g_woh + (size_t)a_m * (CK * 2)
                              + chunk * (KC * 2) + a_g * 16;
            *(uint4*)(smA + sw_off(a_m, a_g)) = *(const uint4*)src;
        }

        {
            int row = ho + ky - 1;
            int col = n + kx - 1;
            bool ok = ((unsigned)row < (unsigned)H_) && ((unsigned)col < (unsigned)W_);
            const float* base = x + (((size_t)(b * C_ + c0 + t4 * 16) * H_ + row) * W_ + col);
            uint32_t o[8];
            #pragma unroll
            for (int q = 0; q < 8; q++) {
                float va = ok ? __ldg(base + (size_t)(2 * q)     * (H_ * W_)) : 0.f;
                float vb = ok ? __ldg(base + (size_t)(2 * q + 1) * (H_ * W_)) : 0.f;
                __half2 h2 = __floats2half2_rn(va, vb);
                o[q] = *(uint32_t*)&h2;
            }
            *(uint4*)(smB + sw_off(n, 2 * t4))     = make_uint4(o[0], o[1], o[2], o[3]);
            *(uint4*)(smB + sw_off(n, 2 * t4 + 1)) = make_uint4(o[4], o[5], o[6], o[7]);
        }
        __syncthreads();

        #pragma unroll
        for (int ks = 0; ks < 4; ks++) {
            uint32_t a0, a1, a2, a3;
            LDSM4(a0, a1, a2, a3, sbA + (uint32_t)(a_row * 128) + ((uint32_t)((2 * ks + agl) ^ ar7) << 4));
            uint32_t b0, b1, b2, b3;
            LDSM4(b0, b1, b2, b3, sbB + (uint32_t)(b_row * 128) + ((uint32_t)((2 * ks + bgl) ^ br7) << 4));
            MMA16816(c[0], a0, a1, a2, a3, b0, b1);
            MMA16816(c[1], a0, a1, a2, a3, b2, b3);
        }
    }

    {
        int ko0 = wm * 16 + (lane >> 2);
        int ko1 = ko0 + 8;
        float bias0 = (ko0 < KO) ? __ldg(b_off + ko0) : 0.f;
        float bias1 = (ko1 < KO) ? __ldg(b_off + ko1) : 0.f;
        #pragma unroll
        for (int ng = 0; ng < 2; ng++) {
            int nb = wn * 16 + ng * 8 + 2 * (lane & 3);
            if (ko0 < KO) {
                float* p = g_off + (((size_t)(b * KO + ko0) * H_ + ho) * W_ + nb);
                *(float2*)p = make_float2(c[ng][0] + bias0, c[ng][1] + bias0);
            }
            if (ko1 < KO) {
                float* p = g_off + (((size_t)(b * KO + ko1) * H_ + ho) * W_ + nb);
                *(float2*)p = make_float2(c[ng][2] + bias1, c[ng][3] + bias1);
            }
        }
    }
}

// ---------------- kernel 2: deformable conv (R11 structure + NHWC coalesced gather) ----------------
#define PITCH 144
__global__ void __launch_bounds__(256)
k_deform(float* __restrict__ out) {
    __shared__ __align__(16) char smA[128 * PITCH];   // 18432
    __shared__ __align__(16) char smB[64 * PITCH];    // 9216
    __shared__ __align__(16) float4 tapW4[576];       // 9216
    __shared__ __align__(16) int4   tapI4[576];       // 9216
    uint32_t sbA = smem_to_u32(smA);
    uint32_t sbB = smem_to_u32(smB);

    int b   = blockIdx.x >> 6;
    int ho  = blockIdx.x & 63;
    int tid = threadIdx.x;
    int wid = tid >> 5;
    int lane = tid & 31;

    // ---- precompute bilinear taps: 4 clamped indices + validity-folded weights ----
    const float* goff = g_off + (size_t)(b * KO) * (H_ * W_) + ho * W_;
    for (int it = tid; it < 576; it += 256) {
        int k  = it >> 6;
        int wo = it & 63;
        float dy = goff[(2 * k)     * (H_ * W_) + wo];
        float dx = goff[(2 * k + 1) * (H_ * W_) + wo];
        float py = (float)(ho - 1 + (k / 3)) + dy;
        float px = (float)(wo - 1 + (k % 3)) + dx;
        float y0f = floorf(py), x0f = floorf(px);
        float wy = py - y0f,    wx = px - x0f;
        int y0 = (int)y0f, x0 = (int)x0f;
        int y1 = y0 + 1,   x1 = x0 + 1;
        float vy0 = (y0 >= 0 && y0 < H_) ? 1.f : 0.f;
        float vy1 = (y1 >= 0 && y1 < H_) ? 1.f : 0.f;
        float vx0 = (x0 >= 0 && x0 < W_) ? 1.f : 0.f;
        float vx1 = (x1 >= 0 && x1 < W_) ? 1.f : 0.f;
        int cy0 = min(max(y0, 0), H_ - 1), cy1 = min(max(y1, 0), H_ - 1);
        int cx0 = min(max(x0, 0), W_ - 1), cx1 = min(max(x1, 0), W_ - 1);
        tapI4[it] = make_int4(cy0 * W_ + cx0, cy0 * W_ + cx1,
                              cy1 * W_ + cx0, cy1 * W_ + cx1);
        tapW4[it] = make_float4((1.f - wy) * (1.f - wx) * vy0 * vx0,
                                (1.f - wy) * wx         * vy0 * vx1,
                                wy * (1.f - wx)         * vy1 * vx0,
                                wy * wx                 * vy1 * vx1);
    }
    __syncthreads();   // taps visible before first gather

    float c[8][4];
    #pragma unroll
    for (int i = 0; i < 8; i++)
        #pragma unroll
        for (int j = 0; j < 4; j++) c[i][j] = 0.f;

    const __half* xhb = g_xh + (size_t)b * (H_ * W_ * C_);
    const int n   = tid & 63;       // pixel this thread gathers
    const int t4  = tid >> 6;       // 16-channel block

    const int g8  = lane >> 3;
    const int lr  = lane & 7;
    const int m0  = wid * 16;
    const uint32_t a_row  = (uint32_t)(m0 + lr + (g8 & 1) * 8);
    const uint32_t a_koff = (uint32_t)((g8 >> 1) * 8);
    const uint32_t b_row  = (uint32_t)(lr + (g8 >> 1) * 8);
    const uint32_t b_koff = (uint32_t)((g8 & 1) * 8);

    const int a_m   = tid >> 1;          // A staging row
    const int a_c16 = (tid & 1) * 4;     // 64B half per thread

    for (int chunk = 0; chunk < NCHUNK; chunk++) {
        const int k9 = chunk >> 1;
        const int c0 = (chunk & 1) * 64;

        __syncthreads();   // prior MMA reads done before restage

        // ---- stage A (fp16 weights): 128 rows x 128B ----
        {
            const char* src = (const char*)g_wh + (size_t)a_m * (CK * 2)
                              + chunk * (KC * 2) + a_c16 * 16;
            char* dst = smA + a_m * PITCH + a_c16 * 16;
            uint4 u0 = *(const uint4*)(src);
            uint4 u1 = *(const uint4*)(src + 16);
            uint4 u2 = *(const uint4*)(src + 32);
            uint4 u3 = *(const uint4*)(src + 48);
            *(uint4*)(dst)      = u0;
            *(uint4*)(dst + 16) = u1;
            *(uint4*)(dst + 32) = u2;
            *(uint4*)(dst + 48) = u3;
        }

        // ---- gather B: 16 channels via NHWC — 2 coalesced LDG.128 per tap ----
        {
            int tb = k9 * 64 + n;
            int4   ti = tapI4[tb];
            float4 tw = tapW4[tb];
            const int cofs = c0 + t4 * 16;
            const uint4* p0 = (const uint4*)(xhb + (size_t)ti.x * C_ + cofs);
            const uint4* p1 = (const uint4*)(xhb + (size_t)ti.y * C_ + cofs);
            const uint4* p2 = (const uint4*)(xhb + (size_t)ti.z * C_ + cofs);
            const uint4* p3 = (const uint4*)(xhb + (size_t)ti.w * C_ + cofs);
            #pragma unroll
            for (int u = 0; u < 2; u++) {
                uint4 q0 = __ldg(p0 + u);
                uint4 q1 = __ldg(p1 + u);
                uint4 q2 = __ldg(p2 + u);
                uint4 q3 = __ldg(p3 + u);
                const __half2* h0 = (const __half2*)&q0;
                const __half2* h1 = (const __half2*)&q1;
                const __half2* h2p = (const __half2*)&q2;
                const __half2* h3 = (const __half2*)&q3;
                uint32_t o[4];
                #pragma unroll
                for (int j = 0; j < 4; j++) {
                    float2 f0 = __half22float2(h0[j]);
                    float2 f1 = __half22float2(h1[j]);
                    float2 f2 = __half22float2(h2p[j]);
                    float2 f3 = __half22float2(h3[j]);
                    float sx = tw.x * f0.x;
                    sx = fmaf(tw.y, f1.x, sx);
                    sx = fmaf(tw.z, f2.x, sx);
                    sx = fmaf(tw.w, f3.x, sx);
                    float sy = tw.x * f0.y;
                    sy = fmaf(tw.y, f1.y, sy);
                    sy = fmaf(tw.z, f2.y, sy);
                    sy = fmaf(tw.w, f3.y, sy);
                    __half2 r = __floats2half2_rn(sx, sy);
                    o[j] = *(uint32_t*)&r;
                }
                *(uint4*)(smB + n * PITCH + t4 * 32 + u * 16) = make_uint4(o[0], o[1], o[2], o[3]);
            }
        }
        __syncthreads();   // A and B ready

        // ---- MMA: 4 k16-steps x 8 n8-tiles ----
        #pragma unroll
        for (int ks = 0; ks < 4; ks++) {
            uint32_t a0, a1, a2, a3;
            LDSM4(a0, a1, a2, a3, sbA + a_row * PITCH + (ks * 16 + a_koff) * 2);
            #pragma unroll
            for (int ng = 0; ng < 4; ng++) {
                uint32_t b0, b1, b2, b3;
                LDSM4(b0, b1, b2, b3, sbB + (ng * 16 + b_row) * PITCH + (ks * 16 + b_koff) * 2);
                MMA16816(c[ng * 2],     a0, a1, a2, a3, b0, b1);
                MMA16816(c[ng * 2 + 1], a0, a1, a2, a3, b2, b3);
            }
        }
    }

    // epilogue
    {
        int r0  = m0 + (lane >> 2);
        int col = 2 * (lane & 3);
        float* ob = out + (((size_t)(b * COUT)) * H_ + ho) * W_;
        #pragma unroll
        for (int t8 = 0; t8 < 8; t8++) {
            int nbase = t8 * 8 + col;
            float* p0 = ob + (size_t)r0 * (H_ * W_) + nbase;
            float* p1 = ob + (size_t)(r0 + 8) * (H_ * W_) + nbase;
            *(float2*)p0 = make_float2(c[t8][0], c[t8][1]);
            *(float2*)p1 = make_float2(c[t8][2], c[t8][3]);
        }
    }
}

// ---------------- launcher ----------------
extern "C" void kernel_launch(void* const* d_in, const int* in_sizes, int n_in,
                              void* d_out, int out_size) {
    const float* x     = (const float*)d_in[0];
    const float* w_off = (const float*)d_in[1];
    const float* b_off = (const float*)d_in[2];
    const float* w_def = (const float*)d_in[3];
    float* out = (float*)d_out;
    (void)in_sizes; (void)n_in; (void)out_size;

    k_prep_w<<<(COUT * CK + 255) / 256, 256>>>(w_def);
    k_prep_woff<<<(MOFF * CK + 255) / 256, 256>>>(w_off);
    k_prep_xh<<<B_ * H_, 256>>>(x);

    k_offmma<<<B_ * H_, 256>>>(x, b_off);
    k_deform<<<B_ * H_, 256>>>(out);
}